// round 2
// baseline (speedup 1.0000x reference)
#include <cuda_runtime.h>
#include <cstdint>

#define NPIX 262144               // 512*512 = 2^18
#define HALFCNT 4194304u          // 16 * NPIX (threefry counter half)

// ---------------- device scratch (allocation-free) ----------------
__device__ float g_xt[4 * 210];
__device__ float g_coef[4 * 8 * 2 * 6];   // [b][r][j][c0,c1,b0,b1,s0,s1]
__device__ float g_wr[4 * 8];             // softmaxed rank weights (first 8 of 9)
__device__ float g_scratch[32 * NPIX];    // w[b][r][n] plane-major (32 MiB)
__device__ float g_part[4 * 64 * 44];     // gram partials per (b, block)
__device__ float g_Cc[4 * 8];             // combine coefs
__device__ float g_Ff[4 * 8];             // noise std coefs
__device__ float g_Kk[4];                 // mean shift

// ---------------- K0a: xt = x @ ctx_w^T + ctx_b ----------------
__global__ void k_xt(const float* __restrict__ x, const float* __restrict__ cw,
                     const float* __restrict__ cb) {
  int f = blockIdx.x;          // 0..209
  int t = threadIdx.x;         // 128 threads
  const float* wrow = cw + f * 512;
  float a0 = 0.f, a1 = 0.f, a2 = 0.f, a3 = 0.f;
  for (int i = t; i < 512; i += 128) {
    float w = wrow[i];
    a0 = fmaf(w, x[i], a0);
    a1 = fmaf(w, x[512 + i], a1);
    a2 = fmaf(w, x[1024 + i], a2);
    a3 = fmaf(w, x[1536 + i], a3);
  }
#pragma unroll
  for (int o = 16; o; o >>= 1) {
    a0 += __shfl_xor_sync(~0u, a0, o);
    a1 += __shfl_xor_sync(~0u, a1, o);
    a2 += __shfl_xor_sync(~0u, a2, o);
    a3 += __shfl_xor_sync(~0u, a3, o);
  }
  __shared__ float sm[4][4];
  int wq = t >> 5, l = t & 31;
  if (l == 0) { sm[wq][0] = a0; sm[wq][1] = a1; sm[wq][2] = a2; sm[wq][3] = a3; }
  __syncthreads();
  if (t == 0) {
    float bb = cb[f];
#pragma unroll
    for (int b = 0; b < 4; b++)
      g_xt[b * 210 + f] = sm[0][b] + sm[1][b] + sm[2][b] + sm[3][b] + bb;
  }
}

// ---------------- K0b: gate, modulation coefs, wr softmax ----------------
__global__ void k_mods() {
  int t = threadIdx.x;  // 128
  __shared__ float gated[4][105];
  for (int i = t; i < 420; i += 128) {
    int b = i / 105, k = i - 105 * b;
    float a1 = g_xt[b * 210 + k], a2 = g_xt[b * 210 + 105 + k];
    gated[b][k] = a1 * tanhf(a2);
  }
  __syncthreads();
  for (int i = t; i < 384; i += 128) {
    int b = i / 96, k = i - 96 * b;
    int r = k / 12, rem = k - 12 * r;
    int g = rem >> 2, j = (rem >> 1) & 1, c = rem & 1;
    float v = gated[b][k];
    if (c == 0) { if (g == 0) v += 0.5f; else if (g == 2) v += 1.0f; }
    g_coef[((b * 8 + r) * 2 + j) * 6 + g * 2 + c] = v;
  }
  if (t < 4) {
    int b = t;
    float w[9];
#pragma unroll
    for (int i = 0; i < 9; i++) w[i] = gated[b][96 + i];
    w[8] += 0.35355339059327373f;  // 1/sqrt(8)
    float ss = 0.f;
#pragma unroll
    for (int i = 0; i < 9; i++) ss += w[i] * w[i];
    float inv = 1.0f / fmaxf(sqrtf(ss), 1e-12f);
    float mx = -3.4e38f;
#pragma unroll
    for (int i = 0; i < 9; i++) { w[i] *= inv; mx = fmaxf(mx, w[i]); }
    float sum = 0.f;
#pragma unroll
    for (int i = 0; i < 9; i++) { w[i] = expf(w[i] - mx); sum += w[i]; }
    float isum = 1.0f / sum;
#pragma unroll
    for (int i = 0; i < 8; i++) g_wr[b * 8 + i] = w[i] * isum;
  }
}

// ---------------- K1: per-pixel w from weights -> scratch ----------------
// weights layout: [(r*4 + i*2 + j)*2*NPIX + 2*n + c]
__global__ void __launch_bounds__(256) k_w(const float* __restrict__ wt) {
  int r = blockIdx.y;
  __shared__ float scf[48];   // [b][j][6] for this r
  if (threadIdx.x < 48) {
    int b = threadIdx.x / 12, rem = threadIdx.x % 12;
    int j = rem / 6, k = rem % 6;
    scf[threadIdx.x] = g_coef[((b * 8 + r) * 2 + j) * 6 + k];
  }
  __syncthreads();
  int n = blockIdx.x * 256 + threadIdx.x;
  const float2* W = (const float2*)wt;
  float2 A0 = W[(size_t)(4 * r + 0) * NPIX + n];  // i=0, j=0
  float2 A1 = W[(size_t)(4 * r + 1) * NPIX + n];  // i=0, j=1
  float2 B0 = W[(size_t)(4 * r + 2) * NPIX + n];  // i=1, j=0
  float2 B1 = W[(size_t)(4 * r + 3) * NPIX + n];  // i=1, j=1
  float dr0 = B0.x - A0.x, di0 = B0.y - A0.y;
  float dr1 = B1.x - A1.x, di1 = B1.y - A1.y;
#pragma unroll
  for (int b = 0; b < 4; b++) {
    const float* c0p = &scf[b * 12];
    // j = 0 (numerator)
    float c0 = c0p[0], c1 = c0p[1], bb0 = c0p[2], bb1 = c0p[3], s0 = c0p[4], s1 = c0p[5];
    float lr = A0.x + c0 * dr0 - c1 * di0;
    float li = A0.y + c0 * di0 + c1 * dr0;
    float nr = bb0 + lr * s0 - li * s1;
    float ni = bb1 + lr * s1 + li * s0;
    // j = 1 (denominator)
    c0 = c0p[6]; c1 = c0p[7]; bb0 = c0p[8]; bb1 = c0p[9]; s0 = c0p[10]; s1 = c0p[11];
    lr = A1.x + c0 * dr1 - c1 * di1;
    li = A1.y + c0 * di1 + c1 * dr1;
    float er = bb0 + lr * s0 - li * s1;
    float ei = bb1 + lr * s1 + li * s0;
    float d2 = er * er + ei * ei;
    float dn = sqrtf(fmaxf(d2, 1e-12f));
    float inv = 1.0f / dn;
    float w = nr * (er * inv) + ni * (ei * inv);
    g_scratch[(size_t)(b * 8 + r) * NPIX + n] = w;
  }
}

// triangular pair index: s <= t
#define TIDX(s, t) ((s) * 8 - (s) * ((s)-1) / 2 + ((t) - (s)))

// ---------------- K2: Gram + sums ----------------
__global__ void __launch_bounds__(256) k_gram() {
  int b = blockIdx.y;
  float a[36], su[8];
#pragma unroll
  for (int k = 0; k < 36; k++) a[k] = 0.f;
#pragma unroll
  for (int k = 0; k < 8; k++) su[k] = 0.f;
  const float* base = g_scratch + (size_t)b * 8 * NPIX;
  for (int it = 0; it < 16; it++) {
    int n = blockIdx.x * 4096 + it * 256 + threadIdx.x;
    float v[8];
#pragma unroll
    for (int s = 0; s < 8; s++) v[s] = base[(size_t)s * NPIX + n];
#pragma unroll
    for (int s = 0; s < 8; s++) {
      su[s] += v[s];
#pragma unroll
      for (int t2 = s; t2 < 8; t2++) a[TIDX(s, t2)] += v[s] * v[t2];
    }
  }
  // warp reduce all 44
#pragma unroll
  for (int k = 0; k < 36; k++)
#pragma unroll
    for (int o = 16; o; o >>= 1) a[k] += __shfl_xor_sync(~0u, a[k], o);
#pragma unroll
  for (int k = 0; k < 8; k++)
#pragma unroll
    for (int o = 16; o; o >>= 1) su[k] += __shfl_xor_sync(~0u, su[k], o);
  __shared__ float red[8][44];
  int wq = threadIdx.x >> 5;
  if ((threadIdx.x & 31) == 0) {
#pragma unroll
    for (int k = 0; k < 36; k++) red[wq][k] = a[k];
#pragma unroll
    for (int k = 0; k < 8; k++) red[wq][36 + k] = su[k];
  }
  __syncthreads();
  if (threadIdx.x < 44) {
    float acc = 0.f;
#pragma unroll
    for (int w2 = 0; w2 < 8; w2++) acc += red[w2][threadIdx.x];
    g_part[(b * 64 + blockIdx.x) * 44 + threadIdx.x] = acc;
  }
}

// ---------------- K3: finalize coefficients ----------------
__global__ void k_fin() {
  __shared__ float sG[176];
  int t = threadIdx.x;
  if (t < 176) {
    int b = t / 44, j = t % 44;
    float acc = 0.f;
    for (int blk = 0; blk < 64; blk++) acc += g_part[(b * 64 + blk) * 44 + j];
    sG[t] = acc;
  }
  __syncthreads();
  if (t < 4) {
    int b = t;
    float G[8][8], S[8];
#pragma unroll
    for (int s = 0; s < 8; s++)
#pragma unroll
      for (int u = s; u < 8; u++) { float g = sG[b * 44 + TIDX(s, u)]; G[s][u] = g; G[u][s] = g; }
#pragma unroll
    for (int s = 0; s < 8; s++) S[s] = sG[b * 44 + 36 + s];
    float nc[8];
#pragma unroll
    for (int s = 0; s < 8; s++) nc[s] = fmaxf(sqrtf(G[s][s]), 1e-12f);
    float Gh[8][8];
#pragma unroll
    for (int s = 0; s < 8; s++)
#pragma unroll
      for (int u = 0; u < 8; u++) Gh[s][u] = G[s][u] / (nc[s] * nc[u]);
    const float alpha = 0.1f / (7.0f * 2.8284271247461903f);  // 0.1/(7*sqrt(8))
    float A[8][8];
#pragma unroll
    for (int s = 0; s < 8; s++)
#pragma unroll
      for (int u = 0; u < 8; u++) A[s][u] = (s == u) ? 1.0f : -alpha * Gh[s][u];
    float C[8], K = 0.f;
#pragma unroll
    for (int s = 0; s < 8; s++) C[s] = 0.f;
#pragma unroll
    for (int r = 0; r < 8; r++) {
      // m_r^2 = (A Gh A^T)_rr
      float q = 0.f;
#pragma unroll
      for (int u = 0; u < 8; u++) {
        float v = 0.f;
#pragma unroll
        for (int s = 0; s < 8; s++) v += A[r][s] * Gh[s][u];
        q += v * A[r][u];
      }
      float mc = fmaxf(sqrtf(fmaxf(q, 0.f)), 1e-12f);
      // D[r][s] = A[r][s]/(nc[s]*mc) ; mean in double
      double meand = 0.0;
      float wr = g_wr[b * 8 + r];
#pragma unroll
      for (int s = 0; s < 8; s++) {
        float D = A[r][s] / (nc[s] * mc);
        C[s] += wr * D;
        meand += (double)D * (double)S[s];
      }
      meand /= (double)NPIX;
      double var = (1.0 - (double)NPIX * meand * meand) / (double)(NPIX - 1);
      if (var < 0.0) var = 0.0;
      double stdd = sqrt(var);
      if (stdd < 1e-12) stdd = 1e-12;
      g_Ff[b * 8 + r] = 0.01f * wr * (float)stdd;
      K += 0.01f * wr * (float)meand;
    }
#pragma unroll
    for (int s = 0; s < 8; s++) g_Cc[b * 8 + s] = C[s];
    g_Kk[b] = K;
  }
}

// ---------------- threefry2x32 (JAX, key = [0, 42]) ----------------
__device__ __forceinline__ void threefry(uint32_t c0, uint32_t c1,
                                         uint32_t& o0, uint32_t& o1) {
  const uint32_t K0 = 0u, K1 = 42u, K2 = 0x1BD11BDAu ^ 0u ^ 42u;
  uint32_t x0 = c0 + K0, x1 = c1 + K1;
#define TFR(rr) { x0 += x1; x1 = __funnelshift_l(x1, x1, rr); x1 ^= x0; }
  TFR(13) TFR(15) TFR(26) TFR(6)   x0 += K1; x1 += K2 + 1u;
  TFR(17) TFR(29) TFR(16) TFR(24)  x0 += K2; x1 += K0 + 2u;
  TFR(13) TFR(15) TFR(26) TFR(6)   x0 += K0; x1 += K1 + 3u;
  TFR(17) TFR(29) TFR(16) TFR(24)  x0 += K1; x1 += K2 + 4u;
  TFR(13) TFR(15) TFR(26) TFR(6)   x0 += K2; x1 += K0 + 5u;
#undef TFR
  o0 = x0; o1 = x1;
}

__device__ __forceinline__ float bits_to_normal(uint32_t bits) {
  float f = __uint_as_float((bits >> 9) | 0x3F800000u) - 1.0f;
  float x = fmaxf(-0.99999994f, fmaf(f, 2.0f, -0.99999994f));
  // XLA/Giles single-precision erfinv
  float w = -__logf(fmaf(x, -x, 1.0f));
  float p;
  if (w < 5.0f) {
    w -= 2.5f;
    p = 2.81022636e-08f;
    p = fmaf(p, w, 3.43273939e-07f);
    p = fmaf(p, w, -3.5233877e-06f);
    p = fmaf(p, w, -4.39150654e-06f);
    p = fmaf(p, w, 0.00021858087f);
    p = fmaf(p, w, -0.00125372503f);
    p = fmaf(p, w, -0.00417768164f);
    p = fmaf(p, w, 0.246640727f);
    p = fmaf(p, w, 1.50140941f);
  } else {
    w = sqrtf(w) - 3.0f;
    p = -0.000200214257f;
    p = fmaf(p, w, 0.000100950558f);
    p = fmaf(p, w, 0.00134934322f);
    p = fmaf(p, w, -0.00367342844f);
    p = fmaf(p, w, 0.00573950773f);
    p = fmaf(p, w, -0.0076224613f);
    p = fmaf(p, w, 0.00943887047f);
    p = fmaf(p, w, 1.00167406f);
    p = fmaf(p, w, 2.83297682f);
  }
  return 1.4142135623730951f * (p * x);
}

// ---------------- K4: combine + noise -> output ----------------
__global__ void __launch_bounds__(256) k_out(float* __restrict__ out) {
  __shared__ float sC[32], sF[32], sK[4];
  if (threadIdx.x < 32) { sC[threadIdx.x] = g_Cc[threadIdx.x]; sF[threadIdx.x] = g_Ff[threadIdx.x]; }
  if (threadIdx.x < 4) sK[threadIdx.x] = g_Kk[threadIdx.x];
  __syncthreads();
  int n = blockIdx.x * 256 + threadIdx.x;
  float acc[4];
#pragma unroll
  for (int b = 0; b < 4; b++) acc[b] = sK[b];
#pragma unroll
  for (int s = 0; s < 8; s++) {
#pragma unroll
    for (int b = 0; b < 4; b++)
      acc[b] += sC[b * 8 + s] * g_scratch[(size_t)(b * 8 + s) * NPIX + n];
  }
#pragma unroll
  for (int b2 = 0; b2 < 2; b2++) {
#pragma unroll
    for (int r = 0; r < 8; r++) {
      uint32_t idx = ((uint32_t)(b2 * 8 + r) << 18) | (uint32_t)n;
      uint32_t o0, o1;
      threefry(idx, idx + HALFCNT, o0, o1);
      acc[b2]     += sF[b2 * 8 + r]       * bits_to_normal(o0);
      acc[b2 + 2] += sF[(b2 + 2) * 8 + r] * bits_to_normal(o1);
    }
  }
#pragma unroll
  for (int b = 0; b < 4; b++) out[(size_t)b * NPIX + n] = acc[b];
}

extern "C" void kernel_launch(void* const* d_in, const int* in_sizes, int n_in,
                              void* d_out, int out_size) {
  const float* x  = (const float*)d_in[0];
  const float* cw = (const float*)d_in[1];
  const float* cb = (const float*)d_in[2];
  const float* wt = (const float*)d_in[3];
  float* out = (float*)d_out;
  k_xt<<<210, 128>>>(x, cw, cb);
  k_mods<<<1, 128>>>();
  k_w<<<dim3(NPIX / 256, 8), 256>>>(wt);
  k_gram<<<dim3(64, 4), 256>>>();
  k_fin<<<1, 256>>>();
  k_out<<<NPIX / 256, 256>>>(out);
}